// round 10
// baseline (speedup 1.0000x reference)
#include <cuda_runtime.h>
#include <cstdint>

#define Bz   64
#define Tz   8192
#define Hz   10
#define CINz 64
#define XCz  66
// front LIF segmentation (decay 0.25 -> 32-step warmup exact)
#define TCH  256           // t-chunk per k1 block (4 segments of 64)
#define K1T  (TCH + 32)    // 288 threads: one GEMM row each
#define K1GX (Tz / TCH)    // 32 GEMM blocks per batch (+1 table block at y==0)
// LSNN segmentation: 16 segments of 512, warmup 2048 (segs 0-4 exact)
#define NS2   16
#define SEGL2 512
#define WARM2 2048
#define WPB   8            // warps per block in k2 (128 blocks -> single wave)

// ---------------- scratch (device globals; no runtime allocation) ----------
__device__ __align__(16) unsigned g_maskf[Bz * Tz];
__device__ __align__(16) float    g_tab_rec[1024 * Hz];
__device__ __align__(16) float    g_tab_inlo[32 * Hz];
__device__ __align__(16) float    g_tab_inhi[32 * Hz];
__device__ __align__(16) float    g_tab_cls[1024 * 2];

// ---------------- k1: fused front GEMM + LIF; extra block builds LUTs ------
__global__ void __launch_bounds__(K1T, 5) k1_front(const float* __restrict__ x,
                                                   const float* __restrict__ w_front,
                                                   const float* __restrict__ b_front,
                                                   const float* __restrict__ w_in,
                                                   const float* __restrict__ w_rec,
                                                   const float* __restrict__ w_cls,
                                                   const float* __restrict__ b_cls,
                                                   float* __restrict__ out) {
    int tid = threadIdx.x, bt = blockIdx.x, b = blockIdx.y;

    // ---- table-builder block (runs concurrently with GEMM blocks) ----
    if (bt == K1GX) {
        if (b != 0) return;
        if (tid < Bz * 2) out[tid] = 0.f;
        for (int m = tid; m < 1024; m += K1T) {
            #pragma unroll
            for (int o = 0; o < Hz; o++) {
                float a = 0.f;
                #pragma unroll
                for (int h = 0; h < Hz; h++)
                    if ((m >> h) & 1) a += w_rec[o * Hz + h];
                g_tab_rec[m * Hz + o] = a;
            }
            float a0 = 0.f, a1 = 0.f;
            #pragma unroll
            for (int h = 0; h < Hz; h++)
                if ((m >> h) & 1) { a0 += w_cls[h]; a1 += w_cls[Hz + h]; }
            g_tab_cls[m * 2 + 0] = a0 + b_cls[0];
            g_tab_cls[m * 2 + 1] = a1 + b_cls[1];
        }
        if (tid < 32) {
            #pragma unroll
            for (int o = 0; o < Hz; o++) {
                float lo = 0.f, hi = 0.f;
                #pragma unroll
                for (int h = 0; h < 5; h++) if ((tid >> h) & 1) lo += w_in[o * Hz + h];
                #pragma unroll
                for (int h = 0; h < 5; h++) if ((tid >> h) & 1) hi += w_in[o * Hz + 5 + h];
                g_tab_inlo[tid * Hz + o] = lo;
                g_tab_inhi[tid * Hz + o] = hi;
            }
        }
        return;
    }

    __shared__ __align__(16) float wsT[CINz * 12];   // transposed, padded to 12/c
    __shared__ float bs[Hz];
    __shared__ float sf[K1T * Hz];                   // 2880 floats

    for (int i = tid; i < CINz * 12; i += K1T) {
        int c = i / 12, h = i - c * 12;
        wsT[i] = (h < Hz) ? w_front[h * CINz + c] : 0.f;
    }
    if (tid < Hz) bs[tid] = b_front[tid];
    __syncthreads();

    // GEMM: one t-row per thread; 3 LDS.128 + 4 LDG + 40 FMA per 4-c group
    {
        int t = bt * TCH - 32 + tid;
        if (t >= 0) {
            const float* xp = x + ((size_t)b * XCz + 1) * Tz + t;  // skip AUD ch 0
            float acc[Hz];
            #pragma unroll
            for (int h = 0; h < Hz; h++) acc[h] = 0.f;
            for (int c0 = 0; c0 < CINz; c0 += 4) {
                float xv[4];
                #pragma unroll
                for (int q = 0; q < 4; q++) xv[q] = __ldg(xp + (size_t)(c0 + q) * Tz);
                #pragma unroll
                for (int q = 0; q < 4; q++) {
                    const float4* wr = (const float4*)(wsT + (c0 + q) * 12);
                    float4 w0 = wr[0], w1 = wr[1];
                    float2 w2 = *(const float2*)(wsT + (c0 + q) * 12 + 8);
                    acc[0] = fmaf(w0.x, xv[q], acc[0]);
                    acc[1] = fmaf(w0.y, xv[q], acc[1]);
                    acc[2] = fmaf(w0.z, xv[q], acc[2]);
                    acc[3] = fmaf(w0.w, xv[q], acc[3]);
                    acc[4] = fmaf(w1.x, xv[q], acc[4]);
                    acc[5] = fmaf(w1.y, xv[q], acc[5]);
                    acc[6] = fmaf(w1.z, xv[q], acc[6]);
                    acc[7] = fmaf(w1.w, xv[q], acc[7]);
                    acc[8] = fmaf(w2.x, xv[q], acc[8]);
                    acc[9] = fmaf(w2.y, xv[q], acc[9]);
                }
            }
            #pragma unroll
            for (int h = 0; h < Hz; h++) sf[tid * Hz + h] = acc[h] + bs[h];
        }
    }
    __syncthreads();

    int wid = tid >> 5, lane = tid & 31;
    if (wid < 2) {
        int seg = wid * 2 + (lane >> 4);     // 0..3
        int h  = lane & 15;
        int hc = (h < Hz) ? h : Hz - 1;
        int t0s = bt * TCH + seg * 64;
        int li0 = seg * 64 + 32;
        int lis = (t0s == 0) ? li0 : li0 - 32;
        float u = 0.f; bool o = false;
        for (int li = lis; li < li0; li++) {          // warmup (no output)
            float xv = sf[li * Hz + hc];
            u = o ? xv : fmaf(0.25f, u, xv);
            o = (h < Hz) && (u > 0.2f);
        }
        unsigned* mp = g_maskf + (size_t)b * Tz + t0s;
        for (int g = 0; g < 16; g++) {
            unsigned q0, q1, q2, q3;
            #pragma unroll
            for (int kk = 0; kk < 4; kk++) {
                int li = li0 + g * 4 + kk;
                float xv = sf[li * Hz + hc];
                u = o ? xv : fmaf(0.25f, u, xv);
                o = (h < Hz) && (u > 0.2f);
                unsigned bal = __ballot_sync(0xFFFFFFFFu, o);
                unsigned mk = (lane < 16) ? (bal & 0x3FFu) : ((bal >> 16) & 0x3FFu);
                if (kk == 0) q0 = mk; else if (kk == 1) q1 = mk;
                else if (kk == 2) q2 = mk; else q3 = mk;
            }
            if (lane == 0 || lane == 16)
                *(uint4*)(mp + g * 4) = make_uint4(q0, q1, q2, q3);
        }
    }
}

// ---------------- k2: segmented LSNN scan + fused classifier (R5 form) -----
// Critical chain: VOTE -> IMAD -> LDS(rec) -> FSETP -> VOTE (~118 cyc/step).
// Classifier (lanes 10/11) reads g_tab_cls via __ldg (L1TEX, off the LDS port).
__global__ void __launch_bounds__(WPB * 32, 1) k2_scan(float* __restrict__ out) {
    __shared__ float s_rec[1024 * Hz];
    __shared__ float s_inlo[32 * Hz];
    __shared__ float s_inhi[32 * Hz];
    int tid = threadIdx.x, lane = tid & 31, wrp = tid >> 5;
    {
        const float4* src = (const float4*)g_tab_rec;
        float4* dst = (float4*)s_rec;
        for (int i = tid; i < (1024 * Hz) / 4; i += WPB * 32) dst[i] = src[i];
        for (int i = tid; i < 32 * Hz; i += WPB * 32) { s_inlo[i] = g_tab_inlo[i]; s_inhi[i] = g_tab_inhi[i]; }
    }
    __syncthreads();

    int w   = blockIdx.x * WPB + wrp;        // 0..Bz*NS2-1
    int b   = w >> 4;                        // NS2 = 16
    int seg = w & (NS2 - 1);
    int t0  = seg * SEGL2;
    int ts  = (t0 - WARM2 > 0) ? (t0 - WARM2) : 0;

    int ln = (lane < Hz) ? lane : 0;
    int csel = (lane == 11) ? 1 : 0;
    const uint4* mfp = (const uint4*)(g_maskf + (size_t)b * Tz);
    int js = ts >> 2, jw = t0 >> 2, je = (t0 + SEGL2) >> 2;

    float v = 0.f, ii = 0.f;
    unsigned mz = 0;
    float uc = 0.f; bool oc = false; int cnt = 0;
    uint4 c0 = mfp[js];
    uint4 c1 = mfp[js + 1];
    for (int j = js; j < je; j++) {
        int j2 = (j + 2 < je) ? j + 2 : je - 1;
        uint4 nxt = mfp[j2];
        bool counting = (j >= jw);
        unsigned mfs[4] = {c0.x, c0.y, c0.z, c0.w};
        #pragma unroll
        for (int k = 0; k < 4; k++) {
            unsigned mf = mfs[k];
            float xin = s_inlo[(mf & 31u) * Hz + ln] + s_inhi[((mf >> 5) & 31u) * Hz + ln];
            float pre = ii + xin;                          // off critical path
            float thr = fmaf(-9.0f, v, 2.0f) - pre;        // off critical path
            float rec = s_rec[mz * Hz + ln];               // critical LDS
            bool  z   = (rec > thr);                       // == (vdec > 0.2)
            mz = __ballot_sync(0xFFFFFFFFu, z) & 0x3FFu;   // critical VOTE
            // classifier LIF (lanes 10/11 meaningful) via L1TEX, off the LDS port
            float xc = __ldg(&g_tab_cls[mz * 2 + csel]);   // 8KB table, L1-hot
            uc = oc ? xc : fmaf(0.25f, uc, xc);
            oc = (uc > 0.2f);
            if (counting && oc) cnt++;
            // LSNN state updates in the shadow of next step's LDS/VOTE
            float ij   = pre + rec;                        // i_jump
            float vdec = fmaf(0.1f, ij, 0.9f * v);
            ii = fmaf(-0.2f, ij, ij);                      // i_dec
            v  = z ? 0.f : vdec;
        }
        c0 = c1; c1 = nxt;
    }
    // counts * 2^-13: every partial sum exact in fp32 atomics
    if (lane == 10) atomicAdd(&out[b * 2 + 0], (float)cnt * (1.0f / (float)Tz));
    if (lane == 11) atomicAdd(&out[b * 2 + 1], (float)cnt * (1.0f / (float)Tz));
}

extern "C" void kernel_launch(void* const* d_in, const int* in_sizes, int n_in,
                              void* d_out, int out_size) {
    const float* x       = (const float*)d_in[0];
    const float* w_front = (const float*)d_in[1];
    const float* b_front = (const float*)d_in[2];
    const float* w_in    = (const float*)d_in[3];
    const float* w_rec   = (const float*)d_in[4];
    const float* w_cls   = (const float*)d_in[5];
    const float* b_cls   = (const float*)d_in[6];
    float* out = (float*)d_out;

    k1_front<<<dim3(K1GX + 1, Bz), K1T>>>(x, w_front, b_front,
                                          w_in, w_rec, w_cls, b_cls, out);
    k2_scan<<<(Bz * NS2) / WPB, WPB * 32>>>(out);
}

// round 11
// speedup vs baseline: 1.1545x; 1.1545x over previous
#include <cuda_runtime.h>
#include <cstdint>

#define Bz   64
#define Tz   8192
#define Hz   10
#define CINz 64
#define XCz  66
// front/cls LIF segmentation (decay 0.25 -> 32-step warmup exact)
#define TCH  256           // t-chunk per k1 block (4 segments of 64)
#define K1T  (TCH + 32)    // 288 threads: one GEMM row each
#define K1GX (Tz / TCH)    // 32 GEMM blocks per batch (+1 table block at y==0)
#define NSEG 128
#define SEGL 64
#define WARM 32
// LSNN segmentation: 16 segments of 512, warmup 2048 (segs 0-4 exact)
#define NS2   16
#define SEGL2 512
#define WARM2 2048
#define WPB   8            // warps per block in k2 (128 blocks -> single wave)

// ---------------- scratch (device globals; no runtime allocation) ----------
__device__ __align__(16) unsigned g_maskf[Bz * Tz];
__device__ __align__(16) unsigned g_maskz[Bz * Tz];
__device__ __align__(16) float    g_tab_rec[1024 * Hz];
__device__ __align__(16) float    g_tab_inlo[32 * 32];   // padded: lanes>=10 get -5e29
__device__ __align__(16) float    g_tab_inhi[32 * 32];
__device__ __align__(16) float    g_tab_cls[1024 * 2];

// ---------------- k1: fused front GEMM + LIF; extra block builds LUTs ------
__global__ void __launch_bounds__(K1T) k1_front(const float* __restrict__ x,
                                                const float* __restrict__ w_front,
                                                const float* __restrict__ b_front,
                                                const float* __restrict__ w_in,
                                                const float* __restrict__ w_rec,
                                                const float* __restrict__ w_cls,
                                                const float* __restrict__ b_cls,
                                                float* __restrict__ out) {
    int tid = threadIdx.x, bt = blockIdx.x, b = blockIdx.y;

    // ---- table-builder block (runs concurrently with GEMM blocks) ----
    if (bt == K1GX) {
        if (b != 0) return;
        if (tid < Bz * 2) out[tid] = 0.f;
        for (int m = tid; m < 1024; m += K1T) {
            #pragma unroll
            for (int o = 0; o < Hz; o++) {
                float a = 0.f;
                #pragma unroll
                for (int h = 0; h < Hz; h++)
                    if ((m >> h) & 1) a += w_rec[o * Hz + h];
                g_tab_rec[m * Hz + o] = a;
            }
            float a0 = 0.f, a1 = 0.f;
            #pragma unroll
            for (int h = 0; h < Hz; h++)
                if ((m >> h) & 1) { a0 += w_cls[h]; a1 += w_cls[Hz + h]; }
            g_tab_cls[m * 2 + 0] = a0 + b_cls[0];
            g_tab_cls[m * 2 + 1] = a1 + b_cls[1];
        }
        if (tid < 32) {
            for (int l = 0; l < 32; l++) {            // padded 32-lane tables
                float lo, hi;
                if (l < Hz) {
                    lo = 0.f; hi = 0.f;
                    #pragma unroll
                    for (int h = 0; h < 5; h++) if ((tid >> h) & 1) lo += w_in[l * Hz + h];
                    #pragma unroll
                    for (int h = 0; h < 5; h++) if ((tid >> h) & 1) hi += w_in[l * Hz + 5 + h];
                } else {
                    lo = -5e29f; hi = -5e29f;          // sentinel: never spike
                }
                g_tab_inlo[tid * 32 + l] = lo;
                g_tab_inhi[tid * 32 + l] = hi;
            }
        }
        return;
    }

    __shared__ float ws[Hz * CINz];
    __shared__ float bs[Hz];
    __shared__ float sf[K1T * Hz];           // 2880 floats
    for (int i = tid; i < Hz * CINz; i += K1T) ws[i] = w_front[i];
    if (tid < Hz) bs[tid] = b_front[tid];
    __syncthreads();

    // GEMM: exactly one t-row per thread (li == tid), no second pass
    {
        int t = bt * TCH - 32 + tid;
        if (t >= 0) {
            const float* xp = x + ((size_t)b * XCz + 1) * Tz + t;  // skip AUD ch 0
            float acc[Hz];
            #pragma unroll
            for (int h = 0; h < Hz; h++) acc[h] = 0.f;
            #pragma unroll 4
            for (int c = 0; c < CINz; c++) {
                float v = __ldg(xp + (size_t)c * Tz);
                #pragma unroll
                for (int h = 0; h < Hz; h++) acc[h] = fmaf(ws[h * CINz + c], v, acc[h]);
            }
            #pragma unroll
            for (int h = 0; h < Hz; h++) sf[tid * Hz + h] = acc[h] + bs[h];
        }
    }
    __syncthreads();

    int wid = tid >> 5, lane = tid & 31;
    if (wid < 2) {
        int seg = wid * 2 + (lane >> 4);     // 0..3
        int h  = lane & 15;
        int hc = (h < Hz) ? h : Hz - 1;
        int t0s = bt * TCH + seg * 64;
        int li0 = seg * 64 + 32;
        int lis = (t0s == 0) ? li0 : li0 - 32;
        float u = 0.f; bool o = false;
        for (int li = lis; li < li0; li++) {          // warmup (no output)
            float xv = sf[li * Hz + hc];
            u = o ? xv : fmaf(0.25f, u, xv);
            o = (h < Hz) && (u > 0.2f);
        }
        unsigned* mp = g_maskf + (size_t)b * Tz + t0s;
        for (int g = 0; g < 16; g++) {
            unsigned q0, q1, q2, q3;
            #pragma unroll
            for (int kk = 0; kk < 4; kk++) {
                int li = li0 + g * 4 + kk;
                float xv = sf[li * Hz + hc];
                u = o ? xv : fmaf(0.25f, u, xv);
                o = (h < Hz) && (u > 0.2f);
                unsigned bal = __ballot_sync(0xFFFFFFFFu, o);
                unsigned mk = (lane < 16) ? (bal & 0x3FFu) : ((bal >> 16) & 0x3FFu);
                if (kk == 0) q0 = mk; else if (kk == 1) q1 = mk;
                else if (kk == 2) q2 = mk; else q3 = mk;
            }
            if (lane == 0 || lane == 16)
                *(uint4*)(mp + g * 4) = make_uint4(q0, q1, q2, q3);
        }
    }
}

// ---------------- k2: segmented LSNN scan (exact R4 form, 160.8us) ---------
// Critical chain: VOTE -> IMAD -> LDS(rec) -> FSETP -> VOTE.
// Lanes >= 10 poisoned (xin = -1e30 -> never spike) so ballot needs no mask.
__global__ void __launch_bounds__(WPB * 32, 1) k2_scan() {
    __shared__ float s_rec[1024 * Hz];
    __shared__ float s_inlo[32 * 32];
    __shared__ float s_inhi[32 * 32];
    int tid = threadIdx.x, lane = tid & 31, wrp = tid >> 5;
    {
        const float4* src = (const float4*)g_tab_rec;
        float4* dst = (float4*)s_rec;
        for (int i = tid; i < (1024 * Hz) / 4; i += WPB * 32) dst[i] = src[i];
        for (int i = tid; i < 32 * 32; i += WPB * 32) { s_inlo[i] = g_tab_inlo[i]; s_inhi[i] = g_tab_inhi[i]; }
    }
    __syncthreads();

    int w   = blockIdx.x * WPB + wrp;        // 0..Bz*NS2-1
    int b   = w >> 4;                        // NS2 = 16
    int seg = w & (NS2 - 1);
    int t0  = seg * SEGL2;
    int ts  = (t0 - WARM2 > 0) ? (t0 - WARM2) : 0;

    int ln = (lane < Hz) ? lane : 0;         // clamped (poisoned lanes never spike)
    const uint4* mfp = (const uint4*)(g_maskf + (size_t)b * Tz);
    uint4* mzp = (uint4*)(g_maskz + (size_t)b * Tz);
    int js = ts >> 2, jw = t0 >> 2, je = (t0 + SEGL2) >> 2;

    float v = 0.f, ii = 0.f;
    unsigned mz = 0;
    uint4 c0 = mfp[js];
    uint4 c1 = mfp[js + 1];
    for (int j = js; j < je; j++) {
        int j2 = (j + 2 < je) ? j + 2 : je - 1;
        uint4 nxt = mfp[j2];
        unsigned mfs[4] = {c0.x, c0.y, c0.z, c0.w};
        unsigned zout[4];
        #pragma unroll
        for (int k = 0; k < 4; k++) {
            unsigned mf = mfs[k];
            float xin = s_inlo[(mf & 31u) * 32 + lane] + s_inhi[((mf >> 5) & 31u) * 32 + lane];
            float pre = ii + xin;                          // off critical path
            float thr = fmaf(-9.0f, v, 2.0f) - pre;        // off critical path
            float rec = s_rec[mz * Hz + ln];               // critical LDS
            bool  z   = (rec > thr);                       // == (vdec > 0.2)
            mz = __ballot_sync(0xFFFFFFFFu, z);            // high bits 0 by construction
            float ij   = pre + rec;                        // i_jump
            float vdec = fmaf(0.1f, ij, 0.9f * v);
            ii = fmaf(-0.2f, ij, ij);                      // i_dec
            v  = z ? 0.f : vdec;
            zout[k] = mz;
        }
        if (lane == 0 && j >= jw) mzp[j] = make_uint4(zout[0], zout[1], zout[2], zout[3]);
        c0 = c1; c1 = nxt;
    }
}

// ---------------- k3: classifier LIF + time-average (exact 32-step warmup) -
__global__ void k3_cls(float* __restrict__ out) {
    __shared__ float s_cls[1024 * 2];
    {
        int tid = threadIdx.x;
        const float4* src = (const float4*)g_tab_cls;
        float4* dst = (float4*)s_cls;
        for (int i = tid; i < (1024 * 2) / 4; i += 128) dst[i] = src[i];
    }
    __syncthreads();
    int idx = blockIdx.x * blockDim.x + threadIdx.x;   // 0..8191
    int b = idx >> 7, seg = idx & (NSEG - 1);
    int t0 = seg * SEGL;
    int ts = (seg == 0) ? 0 : (t0 - WARM);
    float u0 = 0.f, u1 = 0.f;
    bool  o0 = false, o1 = false;
    int   c0 = 0, c1 = 0;
    const unsigned* mzp = g_maskz + (size_t)b * Tz;
    for (int t = ts; t < t0 + SEGL; t++) {
        unsigned mz = mzp[t];
        float x0 = s_cls[mz * 2 + 0];
        float x1 = s_cls[mz * 2 + 1];
        u0 = o0 ? x0 : fmaf(0.25f, u0, x0);
        u1 = o1 ? x1 : fmaf(0.25f, u1, x1);
        o0 = (u0 > 0.2f);
        o1 = (u1 > 0.2f);
        if (t >= t0) { c0 += o0 ? 1 : 0; c1 += o1 ? 1 : 0; }
    }
    // counts * 2^-13: every partial sum exact in fp32 atomics
    atomicAdd(&out[b * 2 + 0], (float)c0 * (1.0f / (float)Tz));
    atomicAdd(&out[b * 2 + 1], (float)c1 * (1.0f / (float)Tz));
}

extern "C" void kernel_launch(void* const* d_in, const int* in_sizes, int n_in,
                              void* d_out, int out_size) {
    const float* x       = (const float*)d_in[0];
    const float* w_front = (const float*)d_in[1];
    const float* b_front = (const float*)d_in[2];
    const float* w_in    = (const float*)d_in[3];
    const float* w_rec   = (const float*)d_in[4];
    const float* w_cls   = (const float*)d_in[5];
    const float* b_cls   = (const float*)d_in[6];
    float* out = (float*)d_out;

    k1_front<<<dim3(K1GX + 1, Bz), K1T>>>(x, w_front, b_front,
                                          w_in, w_rec, w_cls, b_cls, out);
    k2_scan<<<(Bz * NS2) / WPB, WPB * 32>>>();
    k3_cls<<<Bz, 128>>>(out);
}

// round 12
// speedup vs baseline: 1.2628x; 1.0938x over previous
#include <cuda_runtime.h>
#include <cstdint>

#define Bz   64
#define Tz   8192
#define Hz   10
#define CINz 64
#define XCz  66
// front/cls LIF segmentation (decay 0.25 -> 32-step warmup exact)
#define TCH  512           // t-chunk per k1 block (8 segments of 64)
#define ROWS (TCH + 32)    // 544 GEMM rows per block (incl. 32 warmup)
#define HALF (ROWS / 2)    // 272: each thread computes rows (tid, tid+272)
#define K1T  288           // 9 warps
#define K1GX (Tz / TCH)    // 16 GEMM blocks per batch (+1 table block at y==0)
#define NSEG 128
#define SEGL 64
#define WARM 32
// LSNN segmentation: 16 segments of 512, warmup 2048 (segs 0-4 exact)
#define NS2   16
#define SEGL2 512
#define WARM2 2048
#define WPB   8            // warps per block in k2 (128 blocks -> single wave)

// ---------------- scratch (device globals; no runtime allocation) ----------
__device__ __align__(16) unsigned g_maskf[Bz * Tz];
__device__ __align__(16) unsigned g_maskz[Bz * Tz];
__device__ __align__(16) float    g_tab_rec[1024 * Hz];
__device__ __align__(16) float    g_tab_inlo[32 * 32];   // padded: lanes>=10 get -5e29
__device__ __align__(16) float    g_tab_inhi[32 * 32];
__device__ __align__(16) float    g_tab_cls[1024 * 2];

// ---------------- k1: fused front GEMM + LIF; extra block builds LUTs ------
__global__ void __launch_bounds__(K1T) k1_front(const float* __restrict__ x,
                                                const float* __restrict__ w_front,
                                                const float* __restrict__ b_front,
                                                const float* __restrict__ w_in,
                                                const float* __restrict__ w_rec,
                                                const float* __restrict__ w_cls,
                                                const float* __restrict__ b_cls,
                                                float* __restrict__ out) {
    int tid = threadIdx.x, bt = blockIdx.x, b = blockIdx.y;

    // ---- table-builder block (runs concurrently with GEMM blocks) ----
    if (bt == K1GX) {
        if (b != 0) return;
        if (tid < Bz * 2) out[tid] = 0.f;
        for (int m = tid; m < 1024; m += K1T) {
            #pragma unroll
            for (int o = 0; o < Hz; o++) {
                float a = 0.f;
                #pragma unroll
                for (int h = 0; h < Hz; h++)
                    if ((m >> h) & 1) a += w_rec[o * Hz + h];
                g_tab_rec[m * Hz + o] = a;
            }
            float a0 = 0.f, a1 = 0.f;
            #pragma unroll
            for (int h = 0; h < Hz; h++)
                if ((m >> h) & 1) { a0 += w_cls[h]; a1 += w_cls[Hz + h]; }
            g_tab_cls[m * 2 + 0] = a0 + b_cls[0];
            g_tab_cls[m * 2 + 1] = a1 + b_cls[1];
        }
        if (tid < 32) {
            for (int l = 0; l < 32; l++) {            // padded 32-lane tables
                float lo, hi;
                if (l < Hz) {
                    lo = 0.f; hi = 0.f;
                    #pragma unroll
                    for (int h = 0; h < 5; h++) if ((tid >> h) & 1) lo += w_in[l * Hz + h];
                    #pragma unroll
                    for (int h = 0; h < 5; h++) if ((tid >> h) & 1) hi += w_in[l * Hz + 5 + h];
                } else {
                    lo = -5e29f; hi = -5e29f;          // sentinel: never spike
                }
                g_tab_inlo[tid * 32 + l] = lo;
                g_tab_inhi[tid * 32 + l] = hi;
            }
        }
        return;
    }

    __shared__ __align__(16) float wsT[CINz * 12];   // transposed, padded to 12/c
    __shared__ float bs[Hz];
    __shared__ float sf[ROWS * Hz];                  // 5440 floats
    for (int i = tid; i < CINz * 12; i += K1T) {
        int c = i / 12, h = i - c * 12;
        wsT[i] = (h < Hz) ? w_front[h * CINz + c] : 0.f;
    }
    if (tid < Hz) bs[tid] = b_front[tid];
    __syncthreads();

    // GEMM: two t-rows per thread (tid, tid+272); 3 LDS + 2 LDG + 20 FMA / c
    if (tid < HALF) {
        int t0r = bt * TCH - 32 + tid;               // may be <0 only when bt==0
        int t1r = t0r + HALF;                        // always >= 0
        bool ok0 = (t0r >= 0);
        const float* xp = x + ((size_t)b * XCz + 1) * Tz;   // skip AUD ch 0
        float acc0[Hz], acc1[Hz];
        #pragma unroll
        for (int h = 0; h < Hz; h++) { acc0[h] = 0.f; acc1[h] = 0.f; }
        for (int c = 0; c < CINz; c++) {
            float xv0 = ok0 ? __ldg(xp + (size_t)c * Tz + t0r) : 0.f;
            float xv1 = __ldg(xp + (size_t)c * Tz + t1r);
            const float4* wr = (const float4*)(wsT + c * 12);
            float4 w0 = wr[0], w1 = wr[1];
            float2 w2 = *(const float2*)(wsT + c * 12 + 8);
            acc0[0] = fmaf(w0.x, xv0, acc0[0]);  acc1[0] = fmaf(w0.x, xv1, acc1[0]);
            acc0[1] = fmaf(w0.y, xv0, acc0[1]);  acc1[1] = fmaf(w0.y, xv1, acc1[1]);
            acc0[2] = fmaf(w0.z, xv0, acc0[2]);  acc1[2] = fmaf(w0.z, xv1, acc1[2]);
            acc0[3] = fmaf(w0.w, xv0, acc0[3]);  acc1[3] = fmaf(w0.w, xv1, acc1[3]);
            acc0[4] = fmaf(w1.x, xv0, acc0[4]);  acc1[4] = fmaf(w1.x, xv1, acc1[4]);
            acc0[5] = fmaf(w1.y, xv0, acc0[5]);  acc1[5] = fmaf(w1.y, xv1, acc1[5]);
            acc0[6] = fmaf(w1.z, xv0, acc0[6]);  acc1[6] = fmaf(w1.z, xv1, acc1[6]);
            acc0[7] = fmaf(w1.w, xv0, acc0[7]);  acc1[7] = fmaf(w1.w, xv1, acc1[7]);
            acc0[8] = fmaf(w2.x, xv0, acc0[8]);  acc1[8] = fmaf(w2.x, xv1, acc1[8]);
            acc0[9] = fmaf(w2.y, xv0, acc0[9]);  acc1[9] = fmaf(w2.y, xv1, acc1[9]);
        }
        if (ok0) {
            #pragma unroll
            for (int h = 0; h < Hz; h++) sf[tid * Hz + h] = acc0[h] + bs[h];
        }
        #pragma unroll
        for (int h = 0; h < Hz; h++) sf[(tid + HALF) * Hz + h] = acc1[h] + bs[h];
    }
    __syncthreads();

    int wid = tid >> 5, lane = tid & 31;
    if (wid < 4) {                           // 8 segments on 8 half-warps
        int seg = wid * 2 + (lane >> 4);     // 0..7
        int h  = lane & 15;
        int hc = (h < Hz) ? h : Hz - 1;
        int t0s = bt * TCH + seg * 64;
        int li0 = seg * 64 + 32;
        int lis = (t0s == 0) ? li0 : li0 - 32;
        float u = 0.f; bool o = false;
        for (int li = lis; li < li0; li++) {          // warmup (no output)
            float xv = sf[li * Hz + hc];
            u = o ? xv : fmaf(0.25f, u, xv);
            o = (h < Hz) && (u > 0.2f);
        }
        unsigned* mp = g_maskf + (size_t)b * Tz + t0s;
        for (int g = 0; g < 16; g++) {
            unsigned q0, q1, q2, q3;
            #pragma unroll
            for (int kk = 0; kk < 4; kk++) {
                int li = li0 + g * 4 + kk;
                float xv = sf[li * Hz + hc];
                u = o ? xv : fmaf(0.25f, u, xv);
                o = (h < Hz) && (u > 0.2f);
                unsigned bal = __ballot_sync(0xFFFFFFFFu, o);
                unsigned mk = (lane < 16) ? (bal & 0x3FFu) : ((bal >> 16) & 0x3FFu);
                if (kk == 0) q0 = mk; else if (kk == 1) q1 = mk;
                else if (kk == 2) q2 = mk; else q3 = mk;
            }
            if (lane == 0 || lane == 16)
                *(uint4*)(mp + g * 4) = make_uint4(q0, q1, q2, q3);
        }
    }
}

// ---------------- k2: segmented LSNN scan (measured-best form) -------------
// Critical chain: VOTE -> IMAD -> LDS(rec) -> FSETP -> VOTE.
// Lanes >= 10 poisoned (xin = -1e30 -> never spike) so ballot needs no mask.
__global__ void __launch_bounds__(WPB * 32, 1) k2_scan() {
    __shared__ float s_rec[1024 * Hz];
    __shared__ float s_inlo[32 * 32];
    __shared__ float s_inhi[32 * 32];
    int tid = threadIdx.x, lane = tid & 31, wrp = tid >> 5;
    {
        const float4* src = (const float4*)g_tab_rec;
        float4* dst = (float4*)s_rec;
        for (int i = tid; i < (1024 * Hz) / 4; i += WPB * 32) dst[i] = src[i];
        for (int i = tid; i < 32 * 32; i += WPB * 32) { s_inlo[i] = g_tab_inlo[i]; s_inhi[i] = g_tab_inhi[i]; }
    }
    __syncthreads();

    int w   = blockIdx.x * WPB + wrp;        // 0..Bz*NS2-1
    int b   = w >> 4;                        // NS2 = 16
    int seg = w & (NS2 - 1);
    int t0  = seg * SEGL2;
    int ts  = (t0 - WARM2 > 0) ? (t0 - WARM2) : 0;

    int ln = (lane < Hz) ? lane : 0;         // clamped (poisoned lanes never spike)
    const uint4* mfp = (const uint4*)(g_maskf + (size_t)b * Tz);
    uint4* mzp = (uint4*)(g_maskz + (size_t)b * Tz);
    int js = ts >> 2, jw = t0 >> 2, je = (t0 + SEGL2) >> 2;

    float v = 0.f, ii = 0.f;
    unsigned mz = 0;
    uint4 c0 = mfp[js];
    uint4 c1 = mfp[js + 1];
    for (int j = js; j < je; j++) {
        int j2 = (j + 2 < je) ? j + 2 : je - 1;
        uint4 nxt = mfp[j2];
        unsigned mfs[4] = {c0.x, c0.y, c0.z, c0.w};
        unsigned zout[4];
        #pragma unroll
        for (int k = 0; k < 4; k++) {
            unsigned mf = mfs[k];
            float xin = s_inlo[(mf & 31u) * 32 + lane] + s_inhi[((mf >> 5) & 31u) * 32 + lane];
            float pre = ii + xin;                          // off critical path
            float thr = fmaf(-9.0f, v, 2.0f) - pre;        // off critical path
            float rec = s_rec[mz * Hz + ln];               // critical LDS
            bool  z   = (rec > thr);                       // == (vdec > 0.2)
            mz = __ballot_sync(0xFFFFFFFFu, z);            // high bits 0 by construction
            float ij   = pre + rec;                        // i_jump
            float vdec = fmaf(0.1f, ij, 0.9f * v);
            ii = fmaf(-0.2f, ij, ij);                      // i_dec
            v  = z ? 0.f : vdec;
            zout[k] = mz;
        }
        if (lane == 0 && j >= jw) mzp[j] = make_uint4(zout[0], zout[1], zout[2], zout[3]);
        c0 = c1; c1 = nxt;
    }
}

// ---------------- k3: classifier LIF + time-average (exact 32-step warmup) -
__global__ void k3_cls(float* __restrict__ out) {
    __shared__ float s_cls[1024 * 2];
    {
        int tid = threadIdx.x;
        const float4* src = (const float4*)g_tab_cls;
        float4* dst = (float4*)s_cls;
        for (int i = tid; i < (1024 * 2) / 4; i += 128) dst[i] = src[i];
    }
    __syncthreads();
    int idx = blockIdx.x * blockDim.x + threadIdx.x;   // 0..8191
    int b = idx >> 7, seg = idx & (NSEG - 1);
    int t0 = seg * SEGL;
    int ts = (seg == 0) ? 0 : (t0 - WARM);
    float u0 = 0.f, u1 = 0.f;
    bool  o0 = false, o1 = false;
    int   c0 = 0, c1 = 0;
    const unsigned* mzp = g_maskz + (size_t)b * Tz;
    for (int t = ts; t < t0 + SEGL; t++) {
        unsigned mz = mzp[t];
        float x0 = s_cls[mz * 2 + 0];
        float x1 = s_cls[mz * 2 + 1];
        u0 = o0 ? x0 : fmaf(0.25f, u0, x0);
        u1 = o1 ? x1 : fmaf(0.25f, u1, x1);
        o0 = (u0 > 0.2f);
        o1 = (u1 > 0.2f);
        if (t >= t0) { c0 += o0 ? 1 : 0; c1 += o1 ? 1 : 0; }
    }
    // counts * 2^-13: every partial sum exact in fp32 atomics
    atomicAdd(&out[b * 2 + 0], (float)c0 * (1.0f / (float)Tz));
    atomicAdd(&out[b * 2 + 1], (float)c1 * (1.0f / (float)Tz));
}

extern "C" void kernel_launch(void* const* d_in, const int* in_sizes, int n_in,
                              void* d_out, int out_size) {
    const float* x       = (const float*)d_in[0];
    const float* w_front = (const float*)d_in[1];
    const float* b_front = (const float*)d_in[2];
    const float* w_in    = (const float*)d_in[3];
    const float* w_rec   = (const float*)d_in[4];
    const float* w_cls   = (const float*)d_in[5];
    const float* b_cls   = (const float*)d_in[6];
    float* out = (float*)d_out;

    k1_front<<<dim3(K1GX + 1, Bz), K1T>>>(x, w_front, b_front,
                                          w_in, w_rec, w_cls, b_cls, out);
    k2_scan<<<(Bz * NS2) / WPB, WPB * 32>>>();
    k3_cls<<<Bz, 128>>>(out);
}